// round 11
// baseline (speedup 1.0000x reference)
#include <cuda_runtime.h>
#include <cuda_fp16.h>
#include <cstdint>

#define N_NODES 50000
#define C_IN 32
#define HID 64
#define ELLW 96
#define FULL 0xffffffffu

// Scratch (allocation-free rule: __device__ globals)
__device__ int     g_cnt[N_NODES];
__device__ int     g_ell[N_NODES * ELLW];    // 19.2 MB neighbor lists
__device__ float   g_h0[N_NODES * HID];      // fp32 h0 (self-term reads)
__device__ __half2 g_h016[N_NODES * 32];     // half2-packed h0: 64ch = 128B/row
__device__ __half2 g_x16[N_NODES * 16];      // half2-packed x: 32ch = 64B/row

// ---------------------------------------------------------------------------
// Launch 1: zero counters + build fp16 copy of x
__global__ void k_prep(const float2* __restrict__ x2) {
    int i = blockIdx.x * blockDim.x + threadIdx.x;
    int stride = gridDim.x * blockDim.x;
    for (int j = i; j < N_NODES; j += stride) g_cnt[j] = 0;
    for (int j = i; j < N_NODES * 16; j += stride) {
        float2 v = x2[j];
        g_x16[j] = __floats2half2_rn(v.x, v.y);
    }
}

// Launch 2: ELL fill (atomic cursor per destination node)
__global__ void k_ellfill(const int* __restrict__ ei, int E) {
    int e = blockIdx.x * blockDim.x + threadIdx.x;
    if (e >= E) return;
    int src = ei[e];
    int dst = ei[E + e];
    int pos = atomicAdd(g_cnt + dst, 1);
    if (pos < ELLW) g_ell[dst * ELLW + pos] = src;
}

// ---------------------------------------------------------------------------
// Layer 0 fused. Warp per node. Branchless fp16 gather, then LDS.128 GEMV
// with transposed concatenated weights W2T[out][k], k = [Wl(32), Wr(32)].
#define L0_KS 64          // concat k size
#define L0_STRIDE 68      // 17 x 16B, odd -> conflict-free LDS.128
__global__ void k_layer0(const float2* __restrict__ x2,
                         const float* __restrict__ Wl0,
                         const float* __restrict__ b0,
                         const float* __restrict__ Wr0) {
    __shared__ float sW[HID * L0_STRIDE];   // 17.4 KB transposed weights
    __shared__ float sb[HID];
    __shared__ float sAct[8][L0_KS];        // [warp][mean32 | self32]

    int tid = threadIdx.x;
    for (int j = tid; j < HID * L0_KS; j += blockDim.x) {
        int kk = j >> 6, o = j & 63;        // kk 0..63, o = out channel
        float w = (kk < 32) ? Wl0[kk * HID + o] : Wr0[(kk - 32) * HID + o];
        sW[o * L0_STRIDE + kk] = w;
    }
    if (tid < HID) sb[tid] = b0[tid];
    __syncthreads();

    int warp = tid >> 5;
    int lane = tid & 31;
    int node = blockIdx.x * 8 + warp;
    if (node >= N_NODES) return;

    int deg  = g_cnt[node];
    int degL = min(deg, ELLW);
    int row  = node * ELLW;

    int g = lane >> 4;      // neighbor sub-group (0,1)
    int c = lane & 15;      // half2 index within 32-ch row (ch 2c, 2c+1)

    float ax = 0.f, ay = 0.f;
    for (int base = 0; base < degL; base += 32) {
        int idx = base + lane;
        int nb = g_ell[row + min(idx, degL - 1)];   // clamped: always valid
        int m = degL - base;                         // >= 1, warp-uniform
#pragma unroll
        for (int i = 0; i < 32; i += 2) {
            int s = __shfl_sync(FULL, nb, i + g);
            float2 f = __half22float2(g_x16[s * 16 + c]);
            if (i + g < m) { ax += f.x; ay += f.y; }  // predicated add only
        }
    }
    ax += __shfl_xor_sync(FULL, ax, 16);
    ay += __shfl_xor_sync(FULL, ay, 16);

    float inv_cnt = 1.0f / fmaxf((float)deg, 1.0f);
    float2 mean2 = make_float2(ax * inv_cnt, ay * inv_cnt);   // ch {2c,2c+1}
    float2 self2 = x2[node * 16 + c];                         // ch {2c,2c+1}

    // stage activation vector [mean(32) | self(32)]
    if (lane < 16) reinterpret_cast<float2*>(sAct[warp])[c] = mean2;
    else           reinterpret_cast<float2*>(sAct[warp] + 32)[c] = self2;
    __syncwarp();

    float acc0 = sb[lane];
    float acc1 = sb[lane + 32];
    const float* w0p = sW + lane * L0_STRIDE;
    const float* w1p = sW + (lane + 32) * L0_STRIDE;
#pragma unroll
    for (int kk = 0; kk < L0_KS; kk += 4) {
        float4 a4 = *reinterpret_cast<const float4*>(sAct[warp] + kk);
        float4 w0 = *reinterpret_cast<const float4*>(w0p + kk);
        float4 w1 = *reinterpret_cast<const float4*>(w1p + kk);
        acc0 += a4.x * w0.x + a4.y * w0.y + a4.z * w0.z + a4.w * w0.w;
        acc1 += a4.x * w1.x + a4.y * w1.y + a4.z * w1.z + a4.w * w1.w;
    }

    float ss = acc0 * acc0 + acc1 * acc1;
#pragma unroll
    for (int off = 16; off > 0; off >>= 1)
        ss += __shfl_xor_sync(FULL, ss, off);
    float inv = 1.0f / fmaxf(sqrtf(ss), 1e-12f);

    float o0 = fmaxf(acc0 * inv, 0.0f);   // ch lane
    float o1 = fmaxf(acc1 * inv, 0.0f);   // ch lane+32
    g_h0[node * HID + lane]      = o0;
    g_h0[node * HID + lane + 32] = o1;

    // pack fp16 row: lane c holds ch {2c, 2c+1}
    int src_lo = (2 * lane) & 31, src_hi = (2 * lane + 1) & 31;
    float lo0 = __shfl_sync(FULL, o0, src_lo);
    float lo1 = __shfl_sync(FULL, o1, src_lo);
    float hi0 = __shfl_sync(FULL, o0, src_hi);
    float hi1 = __shfl_sync(FULL, o1, src_hi);
    float lo = (lane < 16) ? lo0 : lo1;
    float hi = (lane < 16) ? hi0 : hi1;
    g_h016[node * 32 + lane] = __floats2half2_rn(lo, hi);
}

// ---------------------------------------------------------------------------
// Layer 1 fused. Warp per node. Branchless fp16 gather (128B rows), LDS.128
// GEMV with W2T[out][k], k = [Wl(64) | Wr(64)], normalize, classifier.
#define L1_KS 128
#define L1_STRIDE 132     // 33 x 16B, odd -> conflict-free LDS.128
#define C_STRIDE 68
__global__ void k_layer1(const float* __restrict__ Wl1,
                         const float* __restrict__ b1,
                         const float* __restrict__ Wr1,
                         const float* __restrict__ Wc1,
                         const float* __restrict__ bc1,
                         const float* __restrict__ Wc2,
                         const float* __restrict__ bc2,
                         float* __restrict__ out) {
    __shared__ float sW[HID * L1_STRIDE];    // 33.8 KB transposed [Wl|Wr]
    __shared__ float sWc[32 * C_STRIDE];     // 8.7 KB transposed Wc1
    __shared__ float sb[HID];
    __shared__ float sbc1[32];
    __shared__ float sWc2[32];
    __shared__ float sAct[8][L1_KS];         // [warp][mean64 | self64]; reused for h1

    int tid = threadIdx.x;
    for (int j = tid; j < HID * L1_KS; j += blockDim.x) {
        int kk = j >> 6, o = j & 63;         // kk 0..127
        float w = (kk < 64) ? Wl1[kk * HID + o] : Wr1[(kk - 64) * HID + o];
        sW[o * L1_STRIDE + kk] = w;
    }
    for (int j = tid; j < HID * 32; j += blockDim.x) {
        int kk = j >> 5, o = j & 31;         // kk 0..63
        sWc[o * C_STRIDE + kk] = Wc1[kk * 32 + o];
    }
    if (tid < HID) sb[tid] = b1[tid];
    if (tid < 32) { sbc1[tid] = bc1[tid]; sWc2[tid] = Wc2[tid]; }
    __syncthreads();

    int warp = tid >> 5;
    int lane = tid & 31;
    int node = blockIdx.x * 8 + warp;
    if (node >= N_NODES) return;

    int deg  = g_cnt[node];
    int degL = min(deg, ELLW);
    int row  = node * ELLW;

    float ax = 0.f, ay = 0.f;   // ch {2*lane, 2*lane+1}
    for (int base = 0; base < degL; base += 32) {
        int idx = base + lane;
        int nb = g_ell[row + min(idx, degL - 1)];
        int m = degL - base;                        // >= 1, warp-uniform
#pragma unroll
        for (int i = 0; i < 32; i++) {
            int s = __shfl_sync(FULL, nb, i);
            float2 f = __half22float2(g_h016[s * 32 + lane]);
            if (i < m) { ax += f.x; ay += f.y; }    // predicated add only
        }
    }
    float inv_cnt = 1.0f / fmaxf((float)deg, 1.0f);

    const float2* h02 = reinterpret_cast<const float2*>(g_h0);
    float2 s2 = h02[node * 32 + lane];   // fp32 self ch {2l, 2l+1}

    // stage activation vector [mean(64) | self(64)]
    reinterpret_cast<float2*>(sAct[warp])[lane] = make_float2(ax * inv_cnt, ay * inv_cnt);
    reinterpret_cast<float2*>(sAct[warp] + 64)[lane] = s2;
    __syncwarp();

    float acc0 = sb[lane];
    float acc1 = sb[lane + 32];
    const float* w0p = sW + lane * L1_STRIDE;
    const float* w1p = sW + (lane + 32) * L1_STRIDE;
#pragma unroll
    for (int kk = 0; kk < L1_KS; kk += 4) {
        float4 a4 = *reinterpret_cast<const float4*>(sAct[warp] + kk);
        float4 w0 = *reinterpret_cast<const float4*>(w0p + kk);
        float4 w1 = *reinterpret_cast<const float4*>(w1p + kk);
        acc0 += a4.x * w0.x + a4.y * w0.y + a4.z * w0.z + a4.w * w0.w;
        acc1 += a4.x * w1.x + a4.y * w1.y + a4.z * w1.z + a4.w * w1.w;
    }

    float ss = acc0 * acc0 + acc1 * acc1;
#pragma unroll
    for (int off = 16; off > 0; off >>= 1)
        ss += __shfl_xor_sync(FULL, ss, off);
    float inv = 1.0f / fmaxf(sqrtf(ss), 1e-12f);
    float h1_lo = acc0 * inv;
    float h1_hi = acc1 * inv;

    // stage h1 (overwrite sAct; mean/self no longer needed)
    __syncwarp();
    sAct[warp][lane]      = h1_lo;
    sAct[warp][lane + 32] = h1_hi;
    __syncwarp();

    float cacc = sbc1[lane];
    const float* wcp = sWc + lane * C_STRIDE;
#pragma unroll
    for (int kk = 0; kk < HID; kk += 4) {
        float4 h4 = *reinterpret_cast<const float4*>(sAct[warp] + kk);
        float4 w4 = *reinterpret_cast<const float4*>(wcp + kk);
        cacc += h4.x * w4.x + h4.y * w4.y + h4.z * w4.z + h4.w * w4.w;
    }
    cacc = fmaxf(cacc, 0.0f);
    float p = cacc * sWc2[lane];
#pragma unroll
    for (int off = 16; off > 0; off >>= 1)
        p += __shfl_xor_sync(FULL, p, off);

    if (lane == 0) out[node] = p + bc2[0];
}

// ---------------------------------------------------------------------------
extern "C" void kernel_launch(void* const* d_in, const int* in_sizes, int n_in,
                              void* d_out, int out_size) {
    const float* x    = (const float*)d_in[0];
    const int*   ei   = (const int*)d_in[1];     // int32 edge index
    const float* Wl0  = (const float*)d_in[2];
    const float* b0   = (const float*)d_in[3];
    const float* Wr0  = (const float*)d_in[4];
    const float* Wl1  = (const float*)d_in[5];
    const float* b1   = (const float*)d_in[6];
    const float* Wr1  = (const float*)d_in[7];
    const float* Wc1  = (const float*)d_in[8];
    const float* bc1  = (const float*)d_in[9];
    const float* Wc2  = (const float*)d_in[10];
    const float* bc2  = (const float*)d_in[11];
    float* out = (float*)d_out;

    int E = in_sizes[1] / 2;   // 1,600,000

    k_prep<<<512, 256>>>((const float2*)x);
    k_ellfill<<<(E + 255) / 256, 256>>>(ei, E);
    k_layer0<<<(N_NODES + 7) / 8, 256>>>((const float2*)x, Wl0, b0, Wr0);
    k_layer1<<<(N_NODES + 7) / 8, 256>>>(Wl1, b1, Wr1, Wc1, bc1, Wc2, bc2, out);
}

// round 12
// speedup vs baseline: 1.7491x; 1.7491x over previous
#include <cuda_runtime.h>
#include <cuda_fp16.h>
#include <mma.h>
#include <cstdint>

using namespace nvcuda;

#define N_NODES 50000
#define C_IN 32
#define HID 64
#define ELLW 96
#define NB 64                 // nodes per block in layer kernels
#define FULL 0xffffffffu

// Scratch (allocation-free rule: __device__ globals)
__device__ int     g_cnt[N_NODES];
__device__ int     g_ell[N_NODES * ELLW];    // 19.2 MB neighbor lists
__device__ __half2 g_h016[N_NODES * 32];     // half2-packed h0: 64ch = 128B/row
__device__ __half2 g_x16[N_NODES * 16];      // half2-packed x: 32ch = 64B/row

// ---------------------------------------------------------------------------
// Launch 1: zero counters + build fp16 copy of x
__global__ void k_prep(const float2* __restrict__ x2) {
    int i = blockIdx.x * blockDim.x + threadIdx.x;
    int stride = gridDim.x * blockDim.x;
    for (int j = i; j < N_NODES; j += stride) g_cnt[j] = 0;
    for (int j = i; j < N_NODES * 16; j += stride) {
        float2 v = x2[j];
        g_x16[j] = __floats2half2_rn(v.x, v.y);
    }
}

// Launch 2: ELL fill (atomic cursor per destination node)
__global__ void k_ellfill(const int* __restrict__ ei, int E) {
    int e = blockIdx.x * blockDim.x + threadIdx.x;
    if (e >= E) return;
    int src = ei[e];
    int dst = ei[E + e];
    int pos = atomicAdd(g_cnt + dst, 1);
    if (pos < ELLW) g_ell[dst * ELLW + pos] = src;
}

// ---------------------------------------------------------------------------
// Launch 3: Layer 0. Block = 64 nodes, 256 threads (8 warps).
// Phase A: warp-per-node fp16 gather (as R10) -> fp16 act [mean32|self32].
// Phase B: wmma GEMM 64x64x64 (act @ [Wl0;Wr0]).
// Phase C: +bias, L2-normalize, relu, pack to g_h016.
#define L0_ALD 72     // act ld (halves)
#define L0_CLD 68     // C ld (floats)
__global__ void __launch_bounds__(256) k_layer0(
        const float* __restrict__ Wl0,
        const float* __restrict__ b0,
        const float* __restrict__ Wr0) {
    __shared__ alignas(16) char uAC[NB * L0_CLD * 4];   // act fp16 (NB x L0_ALD) then C fp32
    __shared__ alignas(16) __half sW[64 * L0_ALD];      // weights K=64 x N=64, ld 72
    __shared__ float sb[HID];

    __half* Act = reinterpret_cast<__half*>(uAC);
    float*  Cm  = reinterpret_cast<float*>(uAC);

    int tid  = threadIdx.x;
    int warp = tid >> 5;
    int lane = tid & 31;

    for (int j = tid; j < 64 * HID; j += 256) {
        int kk = j >> 6, o = j & 63;
        float w = (kk < 32) ? Wl0[kk * HID + o] : Wr0[(kk - 32) * HID + o];
        sW[kk * L0_ALD + o] = __float2half(w);
    }
    if (tid < HID) sb[tid] = b0[tid];
    __syncthreads();

    // ---- Phase A: gather means (8 rounds, warp per node) ----
    int g = lane >> 4;      // neighbor sub-group (0,1)
    int c = lane & 15;      // half2 index within 32-ch row
#pragma unroll 1
    for (int r = 0; r < 8; r++) {
        int n = r * 8 + warp;
        int node = blockIdx.x * NB + n;
        if (node < N_NODES) {
            int deg  = g_cnt[node];
            int degL = min(deg, ELLW);
            int row  = node * ELLW;
            float ax = 0.f, ay = 0.f;
            for (int base = 0; base < degL; base += 32) {
                int idx = base + lane;
                int nb = g_ell[row + min(idx, degL - 1)];
                int m = degL - base;
#pragma unroll
                for (int i = 0; i < 32; i += 2) {
                    int s = __shfl_sync(FULL, nb, i + g);
                    float2 f = __half22float2(g_x16[s * 16 + c]);
                    if (i + g < m) { ax += f.x; ay += f.y; }
                }
            }
            ax += __shfl_xor_sync(FULL, ax, 16);
            ay += __shfl_xor_sync(FULL, ay, 16);
            float ic = 1.0f / fmaxf((float)deg, 1.0f);
            __half2* arow = reinterpret_cast<__half2*>(Act + n * L0_ALD);
            if (lane < 16) arow[c] = __floats2half2_rn(ax * ic, ay * ic);   // mean ch{2c,2c+1}
            else           arow[16 + c] = g_x16[node * 16 + c];             // self
        }
    }
    __syncthreads();

    // ---- Phase B: wmma GEMM 64x64x64 ----
    {
        int mi = warp & 3;          // row tile 0..3
        int nj = warp >> 2;         // col tile 0..1 (covers nj and nj+2)
        wmma::fragment<wmma::accumulator, 16, 16, 16, float> c0, c1;
        wmma::fill_fragment(c0, 0.0f);
        wmma::fill_fragment(c1, 0.0f);
#pragma unroll
        for (int k = 0; k < 4; k++) {
            wmma::fragment<wmma::matrix_a, 16, 16, 16, __half, wmma::row_major> a;
            wmma::fragment<wmma::matrix_b, 16, 16, 16, __half, wmma::row_major> b0f, b1f;
            wmma::load_matrix_sync(a, Act + (mi * 16) * L0_ALD + k * 16, L0_ALD);
            wmma::load_matrix_sync(b0f, sW + (k * 16) * L0_ALD + nj * 16, L0_ALD);
            wmma::load_matrix_sync(b1f, sW + (k * 16) * L0_ALD + (nj + 2) * 16, L0_ALD);
            wmma::mma_sync(c0, a, b0f, c0);
            wmma::mma_sync(c1, a, b1f, c1);
        }
        __syncthreads();   // everyone done reading Act before overwriting as C
        wmma::store_matrix_sync(Cm + (mi * 16) * L0_CLD + nj * 16, c0, L0_CLD, wmma::mem_row_major);
        wmma::store_matrix_sync(Cm + (mi * 16) * L0_CLD + (nj + 2) * 16, c1, L0_CLD, wmma::mem_row_major);
    }
    __syncthreads();

    // ---- Phase C: bias + normalize + relu -> g_h016 ----
#pragma unroll 1
    for (int r = 0; r < 8; r++) {
        int n = r * 8 + warp;
        int node = blockIdx.x * NB + n;
        if (node >= N_NODES) continue;
        float a0 = Cm[n * L0_CLD + lane]      + sb[lane];
        float a1 = Cm[n * L0_CLD + lane + 32] + sb[lane + 32];
        float ss = a0 * a0 + a1 * a1;
#pragma unroll
        for (int off = 16; off > 0; off >>= 1)
            ss += __shfl_xor_sync(FULL, ss, off);
        float inv = 1.0f / fmaxf(sqrtf(ss), 1e-12f);
        float o0 = fmaxf(a0 * inv, 0.0f);   // ch lane
        float o1 = fmaxf(a1 * inv, 0.0f);   // ch lane+32
        // pack fp16 row: lane c holds ch {2c, 2c+1}
        int src_lo = (2 * lane) & 31, src_hi = (2 * lane + 1) & 31;
        float lo0 = __shfl_sync(FULL, o0, src_lo);
        float lo1 = __shfl_sync(FULL, o1, src_lo);
        float hi0 = __shfl_sync(FULL, o0, src_hi);
        float hi1 = __shfl_sync(FULL, o1, src_hi);
        float lo = (lane < 16) ? lo0 : lo1;
        float hi = (lane < 16) ? hi0 : hi1;
        g_h016[node * 32 + lane] = __floats2half2_rn(lo, hi);
    }
}

// ---------------------------------------------------------------------------
// Launch 4 (ncu-captured): Layer 1 + classifier. Block = 64 nodes, 256 threads.
// Phase A: fp16 gather of h0 rows -> act [mean64|self64] fp16.
// Phase B: wmma 64x64x128 (act @ [Wl1;Wr1]).
// Phase C: bias + normalize -> h1 fp16.
// Phase D: wmma 64x32x64 (h1 @ Wc1).
// Phase E: bias + relu + dot Wc2 -> out.
#define L1_ALD 136    // act ld (halves): 128 + 8
#define L1_WLD 72     // weight ld
#define L1_CLD 68     // C ld (floats)
#define H1_LD  72     // h1 ld (halves)
#define C2_LD  36     // C2 ld (floats)
#define WC_LD  40     // Wc1 ld (halves)
__global__ void __launch_bounds__(256) k_layer1(
        const float* __restrict__ Wl1,
        const float* __restrict__ b1,
        const float* __restrict__ Wr1,
        const float* __restrict__ Wc1,
        const float* __restrict__ bc1,
        const float* __restrict__ Wc2,
        const float* __restrict__ bc2,
        float* __restrict__ out) {
    __shared__ alignas(16) char uAC[NB * L1_ALD * 2];          // act fp16 (17408B) == C fp32 (64x68x4)
    __shared__ alignas(16) char uW[128 * L1_WLD * 2];          // W fp16 (18432B) -> later H1 fp16 | C2 fp32
    __shared__ alignas(16) __half sWc1h[64 * WC_LD];           // 5120B
    __shared__ float sb[HID];
    __shared__ float sbc1[32];
    __shared__ float sWc2s[32];

    __half* Act = reinterpret_cast<__half*>(uAC);
    float*  Cm  = reinterpret_cast<float*>(uAC);
    __half* W   = reinterpret_cast<__half*>(uW);
    __half* H1  = reinterpret_cast<__half*>(uW);               // 64*72*2 = 9216B
    float*  C2  = reinterpret_cast<float*>(uW + 9216);         // 64*36*4 = 9216B

    int tid  = threadIdx.x;
    int warp = tid >> 5;
    int lane = tid & 31;

    for (int j = tid; j < 128 * HID; j += 256) {
        int kk = j >> 6, o = j & 63;
        float w = (kk < 64) ? Wl1[kk * HID + o] : Wr1[(kk - 64) * HID + o];
        W[kk * L1_WLD + o] = __float2half(w);
    }
    for (int j = tid; j < 64 * 32; j += 256) {
        int kk = j >> 5, o = j & 31;
        sWc1h[kk * WC_LD + o] = __float2half(Wc1[kk * 32 + o]);
    }
    if (tid < HID) sb[tid] = b1[tid];
    if (tid < 32) { sbc1[tid] = bc1[tid]; sWc2s[tid] = Wc2[tid]; }
    __syncthreads();

    // ---- Phase A: gather (8 rounds, warp per node) ----
#pragma unroll 1
    for (int r = 0; r < 8; r++) {
        int n = r * 8 + warp;
        int node = blockIdx.x * NB + n;
        if (node < N_NODES) {
            int deg  = g_cnt[node];
            int degL = min(deg, ELLW);
            int row  = node * ELLW;
            float ax = 0.f, ay = 0.f;   // ch {2*lane, 2*lane+1}
            for (int base = 0; base < degL; base += 32) {
                int idx = base + lane;
                int nb = g_ell[row + min(idx, degL - 1)];
                int m = degL - base;
#pragma unroll
                for (int i = 0; i < 32; i++) {
                    int s = __shfl_sync(FULL, nb, i);
                    float2 f = __half22float2(g_h016[s * 32 + lane]);
                    if (i < m) { ax += f.x; ay += f.y; }
                }
            }
            float ic = 1.0f / fmaxf((float)deg, 1.0f);
            __half2* arow = reinterpret_cast<__half2*>(Act + n * L1_ALD);
            arow[lane]      = __floats2half2_rn(ax * ic, ay * ic);   // mean ch{2l,2l+1}
            arow[32 + lane] = g_h016[node * 32 + lane];              // self
        }
    }
    __syncthreads();

    // ---- Phase B: wmma GEMM 64x64x128 ----
    {
        int mi = warp & 3;
        int nj = warp >> 2;
        wmma::fragment<wmma::accumulator, 16, 16, 16, float> c0, c1;
        wmma::fill_fragment(c0, 0.0f);
        wmma::fill_fragment(c1, 0.0f);
#pragma unroll
        for (int k = 0; k < 8; k++) {
            wmma::fragment<wmma::matrix_a, 16, 16, 16, __half, wmma::row_major> a;
            wmma::fragment<wmma::matrix_b, 16, 16, 16, __half, wmma::row_major> b0f, b1f;
            wmma::load_matrix_sync(a, Act + (mi * 16) * L1_ALD + k * 16, L1_ALD);
            wmma::load_matrix_sync(b0f, W + (k * 16) * L1_WLD + nj * 16, L1_WLD);
            wmma::load_matrix_sync(b1f, W + (k * 16) * L1_WLD + (nj + 2) * 16, L1_WLD);
            wmma::mma_sync(c0, a, b0f, c0);
            wmma::mma_sync(c1, a, b1f, c1);
        }
        __syncthreads();   // done reading Act + W before overwrite
        wmma::store_matrix_sync(Cm + (mi * 16) * L1_CLD + nj * 16, c0, L1_CLD, wmma::mem_row_major);
        wmma::store_matrix_sync(Cm + (mi * 16) * L1_CLD + (nj + 2) * 16, c1, L1_CLD, wmma::mem_row_major);
    }
    __syncthreads();

    // ---- Phase C: bias + normalize -> H1 fp16 (overwrites W region) ----
#pragma unroll 1
    for (int r = 0; r < 8; r++) {
        int n = r * 8 + warp;
        float a0 = Cm[n * L1_CLD + lane]      + sb[lane];
        float a1 = Cm[n * L1_CLD + lane + 32] + sb[lane + 32];
        float ss = a0 * a0 + a1 * a1;
#pragma unroll
        for (int off = 16; off > 0; off >>= 1)
            ss += __shfl_xor_sync(FULL, ss, off);
        float inv = 1.0f / fmaxf(sqrtf(ss), 1e-12f);
        H1[n * H1_LD + lane]      = __float2half(a0 * inv);
        H1[n * H1_LD + lane + 32] = __float2half(a1 * inv);
    }
    __syncthreads();

    // ---- Phase D: wmma GEMM 64x32x64 (h1 @ Wc1) ----
    {
        int mi = warp & 3;
        int nj = warp >> 2;   // 0..1
        wmma::fragment<wmma::accumulator, 16, 16, 16, float> cf;
        wmma::fill_fragment(cf, 0.0f);
#pragma unroll
        for (int k = 0; k < 4; k++) {
            wmma::fragment<wmma::matrix_a, 16, 16, 16, __half, wmma::row_major> a;
            wmma::fragment<wmma::matrix_b, 16, 16, 16, __half, wmma::row_major> bf;
            wmma::load_matrix_sync(a, H1 + (mi * 16) * H1_LD + k * 16, H1_LD);
            wmma::load_matrix_sync(bf, sWc1h + (k * 16) * WC_LD + nj * 16, WC_LD);
            wmma::mma_sync(cf, a, bf, cf);
        }
        wmma::store_matrix_sync(C2 + (mi * 16) * C2_LD + nj * 16, cf, C2_LD, wmma::mem_row_major);
    }
    __syncthreads();

    // ---- Phase E: bias + relu + dot(Wc2) -> out ----
#pragma unroll 1
    for (int r = 0; r < 8; r++) {
        int n = r * 8 + warp;
        int node = blockIdx.x * NB + n;
        if (node >= N_NODES) continue;
        float v = C2[n * C2_LD + lane] + sbc1[lane];
        v = fmaxf(v, 0.0f);
        float p = v * sWc2s[lane];
#pragma unroll
        for (int off = 16; off > 0; off >>= 1)
            p += __shfl_xor_sync(FULL, p, off);
        if (lane == 0) out[node] = p + bc2[0];
    }
}

// ---------------------------------------------------------------------------
extern "C" void kernel_launch(void* const* d_in, const int* in_sizes, int n_in,
                              void* d_out, int out_size) {
    const float* x    = (const float*)d_in[0];
    const int*   ei   = (const int*)d_in[1];     // int32 edge index
    const float* Wl0  = (const float*)d_in[2];
    const float* b0   = (const float*)d_in[3];
    const float* Wr0  = (const float*)d_in[4];
    const float* Wl1  = (const float*)d_in[5];
    const float* b1   = (const float*)d_in[6];
    const float* Wr1  = (const float*)d_in[7];
    const float* Wc1  = (const float*)d_in[8];
    const float* bc1  = (const float*)d_in[9];
    const float* Wc2  = (const float*)d_in[10];
    const float* bc2  = (const float*)d_in[11];
    float* out = (float*)d_out;

    int E = in_sizes[1] / 2;   // 1,600,000
    int nblk = (N_NODES + NB - 1) / NB;

    k_prep<<<512, 256>>>((const float2*)x);
    k_ellfill<<<(E + 255) / 256, 256>>>(ei, E);
    k_layer0<<<nblk, 256>>>(Wl0, b0, Wr0);
    k_layer1<<<nblk, 256>>>(Wl1, b1, Wr1, Wc1, bc1, Wc2, bc2, out);
}